// round 4
// baseline (speedup 1.0000x reference)
#include <cuda_runtime.h>
#include <math.h>
#include <stdint.h>

typedef unsigned long long ull;

// Problem constants
#define Bn 2
#define Tn 32
#define Nn 64
#define FINn 64
#define FOUTn 64
#define EDIMn 16
#define BT (Bn*Tn)            // 64
#define ROWS (BT*Nn)          // 4096
#define KE (Nn*EDIMn)         // 1024
#define EO (EDIMn*FOUTn)      // 1024
#define EDGE_TOTAL (Bn*Nn*Nn*EDIMn)   // 131072
#define EDGE_BLOCKS (EDGE_TOTAL/256)  // 512

// -------- device scratch --------
__device__ float g_xn[ROWS*FINn];        // [bt][j][f]       1 MB
__device__ float g_h[Bn*Nn*KE];          // [b][i][(j,e)]    512 KB
__device__ float g_P[ROWS*EO];           // [bt][(j,e)][o]   16 MB
__device__ float g_part[5][BT*Nn*FOUTn]; // agg K-splits + node-lin
__device__ float g_T2[BT*FOUTn];         // eb2 contribution

__device__ __forceinline__ float gelu_exact(float v) {
    return 0.5f * v * (1.0f + erff(v * 0.70710678118654752f));
}

// ---- packed fp32x2 helpers (FFMA2) ----
__device__ __forceinline__ void ffma2(ull& d, ull a, ull b) {
    asm("fma.rn.f32x2 %0, %1, %2, %0;" : "+l"(d) : "l"(a), "l"(b));
}
__device__ __forceinline__ ull dup2(float v) {
    uint32_t u = __float_as_uint(v);
    return ((ull)u << 32) | (ull)u;
}
__device__ __forceinline__ float lo32(ull v) { return __uint_as_float((uint32_t)v); }
__device__ __forceinline__ float hi32(ull v) { return __uint_as_float((uint32_t)(v >> 32)); }

// ============ K1: fused prologue (norm + T2 + edge-gelu) ============
__global__ void __launch_bounds__(256) k_pre(const float* __restrict__ x,
                                             const float* __restrict__ adj,
                                             const float* __restrict__ ew1,
                                             const float* __restrict__ eb1,
                                             const float* __restrict__ eb2,
                                             const float* __restrict__ gw,
                                             const float* __restrict__ gb,
                                             const float* __restrict__ gms) {
    int blk = blockIdx.x;
    int tid = threadIdx.x;

    if (blk >= BT) {
        int idx = (blk - BT) * 256 + tid;
        int e = idx & (EDIMn - 1);
        float a = adj[idx >> 4];
        g_h[idx] = gelu_exact(a * ew1[e] + eb1[e]);
        return;
    }

    int bt = blk;
    int f = tid & 63;
    int g = tid >> 6;
    __shared__ float sA[4][64];
    __shared__ float sB[4][64];
    __shared__ float sMul[64], sSub[64], sAdd[64], sSf[64];

    const float* xp = x + bt * (Nn * FINn) + f;
    float s = 0.f, ss = 0.f;
#pragma unroll
    for (int n = g * 16; n < g * 16 + 16; n++) {
        float v = xp[n * FINn];
        s += v; ss += v * v;
    }
    sA[g][f] = s; sB[g][f] = ss;
    __syncthreads();

    if (g == 0) {
        float st  = sA[0][f] + sA[1][f] + sA[2][f] + sA[3][f];
        float sst = sB[0][f] + sB[1][f] + sB[2][f] + sB[3][f];
        float mean = st * (1.0f / Nn);
        float var  = sst * (1.0f / Nn) - mean * mean;
        float rstd = rsqrtf(var + 1e-5f);
        float w = gw[f], bb = gb[f];
        float sub = mean * gms[0];
        sMul[f] = rstd * w;
        sSub[f] = sub;
        sAdd[f] = bb;
        sSf[f]  = (float)Nn * ((mean - sub) * rstd * w + bb);
    }
    __syncthreads();

    float mul = sMul[f], sub = sSub[f], add = sAdd[f];
    float* xnp = g_xn + bt * (Nn * FINn) + f;
#pragma unroll
    for (int n = g * 16; n < g * 16 + 16; n++)
        xnp[n * FINn] = (xp[n * FINn] - sub) * mul + add;

    int o = f;
    float acc = 0.f;
#pragma unroll
    for (int ff = g * 16; ff < g * 16 + 16; ff++)
        acc += sSf[ff] * eb2[ff * FOUTn + o];
    __syncthreads();
    sA[g][o] = acc;
    __syncthreads();
    if (g == 0)
        g_T2[bt * FOUTn + o] = sA[0][o] + sA[1][o] + sA[2][o] + sA[3][o];
}

// -------- packed inner loop: thread tile 4 rows x 8 cols (4 col-pairs) --------
// AsD: [64][64] b64 duplicated A values; Bs: row-major floats, BSW cols.
#define PACK_MAIN(AsD, Bs, BSW)                                               \
    _Pragma("unroll 8")                                                       \
    for (int k = 0; k < 64; k++) {                                            \
        ull a0 = AsD[(ty4 + 0) * 64 + k];                                     \
        ull a1 = AsD[(ty4 + 1) * 64 + k];                                     \
        ull a2 = AsD[(ty4 + 2) * 64 + k];                                     \
        ull a3 = AsD[(ty4 + 3) * 64 + k];                                     \
        ulonglong2 bv0 = *(const ulonglong2*)&Bs[k * BSW + tx8];              \
        ulonglong2 bv1 = *(const ulonglong2*)&Bs[k * BSW + tx8 + 4];          \
        ffma2(acc[0][0], a0, bv0.x); ffma2(acc[0][1], a0, bv0.y);             \
        ffma2(acc[0][2], a0, bv1.x); ffma2(acc[0][3], a0, bv1.y);             \
        ffma2(acc[1][0], a1, bv0.x); ffma2(acc[1][1], a1, bv0.y);             \
        ffma2(acc[1][2], a1, bv1.x); ffma2(acc[1][3], a1, bv1.y);             \
        ffma2(acc[2][0], a2, bv0.x); ffma2(acc[2][1], a2, bv0.y);             \
        ffma2(acc[2][2], a2, bv1.x); ffma2(acc[2][3], a2, bv1.y);             \
        ffma2(acc[3][0], a3, bv0.x); ffma2(acc[3][1], a3, bv0.y);             \
        ffma2(acc[3][2], a3, bv1.x); ffma2(acc[3][3], a3, bv1.y);             \
    }

#define STORE_ROW(ptr, i)                                                     \
    *(float4*)(ptr) = make_float4(lo32(acc[i][0]), hi32(acc[i][0]),           \
                                  lo32(acc[i][1]), hi32(acc[i][1]));          \
    *(float4*)((ptr) + 4) = make_float4(lo32(acc[i][2]), hi32(acc[i][2]),     \
                                        lo32(acc[i][3]), hi32(acc[i][3]));

// ============ K2: GEMM1  P(4096x1024) = xn(4096x64) @ Wp(64x1024) ============
// tile 64 rows x 128 cols (2 ew2 e-blocks), 256 threads, thread tile 4x8
#define G1_SMEM (32768 + 32768)
__global__ void __launch_bounds__(256) k_gemm1(const float* __restrict__ ew2) {
    extern __shared__ char ds[];
    ull*   AsD = (ull*)ds;                 // [64][64] dup pairs (32KB)
    float* Bs  = (float*)(ds + 32768);     // [64][128] (32KB)

    int tid = threadIdx.x;
    int e0 = blockIdx.x * 2;               // two e-blocks per tile
    int r0 = blockIdx.y * 64;

    // A fill: 1024 float4, duplicated into b64 pairs
    const float4* Ag = (const float4*)(g_xn + r0 * FINn);
#pragma unroll
    for (int l = 0; l < 4; l++) {
        int e4 = tid + l * 256;
        float4 v = Ag[e4];
        int r = e4 >> 4, f = (e4 & 15) * 4;
        ulonglong2 p01, p23;
        p01.x = dup2(v.x); p01.y = dup2(v.y);
        p23.x = dup2(v.z); p23.y = dup2(v.w);
        *(ulonglong2*)&AsD[r * 64 + f]     = p01;
        *(ulonglong2*)&AsD[r * 64 + f + 2] = p23;
    }
    // B fill: two contiguous 64x64 ew2 blocks -> Bs[f][h*64 + c]
#pragma unroll
    for (int h = 0; h < 2; h++) {
        const float4* Bg = (const float4*)(ew2 + (e0 + h) * 4096);
#pragma unroll
        for (int l = 0; l < 4; l++) {
            int e4 = tid + l * 256;
            int f = e4 >> 4, c = (e4 & 15) * 4;
            *(float4*)&Bs[f * 128 + h * 64 + c] = Bg[e4];
        }
    }
    __syncthreads();

    int ty4 = (tid >> 4) * 4;              // rows
    int tx8 = (tid & 15) * 8;              // cols
    ull acc[4][4] = {};
    PACK_MAIN(AsD, Bs, 128)

    float* Cp = g_P + r0 * EO + e0 * 64 + tx8;
#pragma unroll
    for (int i = 0; i < 4; i++) {
        float* p = Cp + (ty4 + i) * EO;
        STORE_ROW(p, i)
    }
}

// ============ K3: GEMM2 (agg K-split x4 + node-lin), 128 threads ============
// blocks 0..255 : bt=bid>>2, ks=bid&3 : part[ks] += H_b[:,ks*256:+256] @ P_bt slice
// blocks 256..319: part[4] = xn[bt] @ nw
#define G2_SMEM (32768 + 16384)
__global__ void __launch_bounds__(128) k_gemm2(const float* __restrict__ nw) {
    extern __shared__ char ds[];
    ull*   AsD = (ull*)ds;                 // [64][64] dup (32KB)
    float* Bs  = (float*)(ds + 32768);     // [64][64] (16KB)

    int tid = threadIdx.x;
    int bid = blockIdx.x;
    int ty4 = (tid >> 3) * 4;              // 16 row-groups
    int tx8 = (tid & 7) * 8;               // 8 col-groups
    ull acc[4][4] = {};

    const float *Asrc, *Bsrc;
    float* Cdst;
    int nchunk, strideA;
    if (bid < BT * 4) {
        int bt = bid >> 2, ks = bid & 3, b = bt >> 5;
        Asrc = g_h + b * (Nn * KE) + ks * 256;
        strideA = KE;
        Bsrc = g_P + bt * (Nn * EO) + ks * 256 * 64;
        Cdst = g_part[ks] + bt * (Nn * FOUTn);
        nchunk = 4;
    } else {
        int bt = bid - BT * 4;
        Asrc = g_xn + bt * 4096;
        strideA = 64;
        Bsrc = nw;
        Cdst = g_part[4] + bt * (Nn * FOUTn);
        nchunk = 1;
    }

    for (int c = 0; c < nchunk; c++) {
        // A fill: 64 rows x 64 k floats (1024 float4), duplicated
#pragma unroll
        for (int l = 0; l < 8; l++) {
            int e4 = tid + l * 128;
            int r = e4 >> 4, kk = (e4 & 15) * 4;
            float4 v = *(const float4*)(Asrc + r * strideA + c * 64 + kk);
            ulonglong2 p01, p23;
            p01.x = dup2(v.x); p01.y = dup2(v.y);
            p23.x = dup2(v.z); p23.y = dup2(v.w);
            *(ulonglong2*)&AsD[r * 64 + kk]     = p01;
            *(ulonglong2*)&AsD[r * 64 + kk + 2] = p23;
        }
        // B fill: contiguous 64x64 block
        const float4* Bg = (const float4*)(Bsrc + c * 64 * 64);
#pragma unroll
        for (int l = 0; l < 8; l++) {
            int e4 = tid + l * 128;
            *((float4*)Bs + e4) = Bg[e4];
        }
        __syncthreads();
        PACK_MAIN(AsD, Bs, 64)
        __syncthreads();
    }

    float* Cp = Cdst + tx8;
#pragma unroll
    for (int i = 0; i < 4; i++) {
        float* p = Cp + (ty4 + i) * FOUTn;
        STORE_ROW(p, i)
    }
}

// ============ K4: elementwise epilogue ============
__global__ void __launch_bounds__(256) k_epi(const float* __restrict__ nb,
                                             float* __restrict__ out) {
    int idx = blockIdx.x * 256 + threadIdx.x;
    int e0 = idx * 4;
    int bt = e0 >> 12;
    int o  = e0 & 63;

    float4 p0 = *(const float4*)(g_part[0] + e0);
    float4 p1 = *(const float4*)(g_part[1] + e0);
    float4 p2 = *(const float4*)(g_part[2] + e0);
    float4 p3 = *(const float4*)(g_part[3] + e0);
    float4 p4 = *(const float4*)(g_part[4] + e0);
    float4 nbv = *(const float4*)(nb + o);
    float4 t2v = *(const float4*)(g_T2 + bt * FOUTn + o);

    float v0 = p0.x + p1.x + p2.x + p3.x + p4.x + nbv.x + t2v.x;
    float v1 = p0.y + p1.y + p2.y + p3.y + p4.y + nbv.y + t2v.y;
    float v2 = p0.z + p1.z + p2.z + p3.z + p4.z + nbv.z + t2v.z;
    float v3 = p0.w + p1.w + p2.w + p3.w + p4.w + nbv.w + t2v.w;
    *(float4*)(out + e0) = make_float4(gelu_exact(v0), gelu_exact(v1),
                                       gelu_exact(v2), gelu_exact(v3));
}

extern "C" void kernel_launch(void* const* d_in, const int* in_sizes, int n_in,
                              void* d_out, int out_size) {
    const float* x   = (const float*)d_in[0];
    const float* adj = (const float*)d_in[1];
    const float* ew1 = (const float*)d_in[2];
    const float* eb1 = (const float*)d_in[3];
    const float* ew2 = (const float*)d_in[4];
    const float* eb2 = (const float*)d_in[5];
    const float* nw  = (const float*)d_in[6];
    const float* nb  = (const float*)d_in[7];
    const float* gw  = (const float*)d_in[8];
    const float* gb  = (const float*)d_in[9];
    const float* gms = (const float*)d_in[10];
    float* out = (float*)d_out;

    static int attr_done = 0;
    if (!attr_done) {
        cudaFuncSetAttribute(k_gemm1, cudaFuncAttributeMaxDynamicSharedMemorySize, G1_SMEM);
        cudaFuncSetAttribute(k_gemm2, cudaFuncAttributeMaxDynamicSharedMemorySize, G2_SMEM);
        attr_done = 1;
    }

    k_pre<<<BT + EDGE_BLOCKS, 256>>>(x, adj, ew1, eb1, eb2, gw, gb, gms);
    k_gemm1<<<dim3(EO/128, ROWS/64), 256, G1_SMEM>>>(ew2);
    k_gemm2<<<BT * 4 + BT, 128, G2_SMEM>>>(nw);
    k_epi<<<(ROWS * FOUTn) / (256 * 4), 256>>>(nb, out);
}

// round 5
// speedup vs baseline: 2.2594x; 2.2594x over previous
#include <cuda_runtime.h>
#include <cuda_bf16.h>
#include <math.h>
#include <stdint.h>

// Problem constants
#define Bn 2
#define Tn 32
#define Nn 64
#define FINn 64
#define FOUTn 64
#define EDIMn 16
#define BT (Bn*Tn)            // 64
#define ROWS (BT*Nn)          // 4096
#define KE (Nn*EDIMn)         // 1024
#define EO (EDIMn*FOUTn)      // 1024

// -------- device scratch --------
__device__ __nv_bfloat16 g_xnh[ROWS*FINn];    // xn hi  [bt*64+j][f]
__device__ __nv_bfloat16 g_xnl[ROWS*FINn];    // xn lo
__device__ __nv_bfloat16 g_hh[Bn*Nn*KE];      // h hi   [b][i][je]
__device__ __nv_bfloat16 g_hl[Bn*Nn*KE];
__device__ __nv_bfloat16 g_w2h[EDIMn*FINn*FOUTn]; // ew2 hi [e][f][o]
__device__ __nv_bfloat16 g_w2l[EDIMn*FINn*FOUTn];
__device__ __nv_bfloat16 g_nwh[FINn*FOUTn];   // nw hi [f][o]
__device__ __nv_bfloat16 g_nwl[FINn*FOUTn];
__device__ __nv_bfloat16 g_Ph[ROWS*EO];       // P hi [m=bt*64+j][n=e*64+o] == per-bt [je][o]
__device__ __nv_bfloat16 g_Pl[ROWS*EO];       // P lo
__device__ float g_part[5][BT*Nn*FOUTn];      // agg K-splits + node-lin
__device__ float g_T2[BT*FOUTn];              // eb2 contribution

__device__ __forceinline__ float gelu_exact(float v) {
    return 0.5f * v * (1.0f + erff(v * 0.70710678118654752f));
}
__device__ __forceinline__ void split_bf16(float v, __nv_bfloat16& h, __nv_bfloat16& l) {
    h = __float2bfloat16(v);
    l = __float2bfloat16(v - __bfloat162float(h));
}
__device__ __forceinline__ uint32_t smem_u32(const void* p) {
    uint32_t a;
    asm("{ .reg .u64 t; cvta.to.shared.u64 t, %1; cvt.u32.u64 %0, t; }" : "=r"(a) : "l"(p));
    return a;
}

#define LDM_X4(r0,r1,r2,r3,addr) \
    asm volatile("ldmatrix.sync.aligned.m8n8.x4.shared.b16 {%0,%1,%2,%3}, [%4];" \
        : "=r"(r0),"=r"(r1),"=r"(r2),"=r"(r3) : "r"(addr))
#define LDM_X4T(r0,r1,r2,r3,addr) \
    asm volatile("ldmatrix.sync.aligned.m8n8.x4.trans.shared.b16 {%0,%1,%2,%3}, [%4];" \
        : "=r"(r0),"=r"(r1),"=r"(r2),"=r"(r3) : "r"(addr))

__device__ __forceinline__ void mma_bf16(float* c, const uint32_t* a, uint32_t b0, uint32_t b1) {
    asm volatile("mma.sync.aligned.m16n8k16.row.col.f32.bf16.bf16.f32 "
        "{%0,%1,%2,%3}, {%4,%5,%6,%7}, {%8,%9}, {%0,%1,%2,%3};"
        : "+f"(c[0]), "+f"(c[1]), "+f"(c[2]), "+f"(c[3])
        : "r"(a[0]), "r"(a[1]), "r"(a[2]), "r"(a[3]), "r"(b0), "r"(b1));
}

// ============ K1: fused prologue ============
// blk 0..63: norm+T2 | 64..575: edge | 576..831: ew2 convert | 832..847: nw convert
__global__ void __launch_bounds__(256) k_pre(const float* __restrict__ x,
                                             const float* __restrict__ adj,
                                             const float* __restrict__ ew1,
                                             const float* __restrict__ eb1,
                                             const float* __restrict__ ew2,
                                             const float* __restrict__ eb2,
                                             const float* __restrict__ nw,
                                             const float* __restrict__ gw,
                                             const float* __restrict__ gb,
                                             const float* __restrict__ gms) {
    int blk = blockIdx.x;
    int tid = threadIdx.x;

    if (blk >= 832) {                       // nw convert: 4096 elems
        int idx = (blk - 832) * 256 + tid;
        __nv_bfloat16 h, l; split_bf16(nw[idx], h, l);
        g_nwh[idx] = h; g_nwl[idx] = l;
        return;
    }
    if (blk >= 576) {                       // ew2 convert: 65536 elems
        int idx = (blk - 576) * 256 + tid;
        __nv_bfloat16 h, l; split_bf16(ew2[idx], h, l);
        g_w2h[idx] = h; g_w2l[idx] = l;
        return;
    }
    if (blk >= BT) {                        // edge: 131072 elems
        int idx = (blk - BT) * 256 + tid;
        int e = idx & (EDIMn - 1);
        float a = adj[idx >> 4];
        float v = gelu_exact(a * ew1[e] + eb1[e]);
        __nv_bfloat16 h, l; split_bf16(v, h, l);
        g_hh[idx] = h; g_hl[idx] = l;
        return;
    }

    // ---- norm + T2 ----
    int bt = blk;
    int f = tid & 63;
    int g = tid >> 6;
    __shared__ float sA[4][64];
    __shared__ float sB[4][64];
    __shared__ float sMul[64], sSub[64], sAdd[64], sSf[64];

    const float* xp = x + bt * (Nn * FINn) + f;
    float s = 0.f, ss = 0.f;
#pragma unroll
    for (int n = g * 16; n < g * 16 + 16; n++) {
        float v = xp[n * FINn];
        s += v; ss += v * v;
    }
    sA[g][f] = s; sB[g][f] = ss;
    __syncthreads();

    if (g == 0) {
        float st  = sA[0][f] + sA[1][f] + sA[2][f] + sA[3][f];
        float sst = sB[0][f] + sB[1][f] + sB[2][f] + sB[3][f];
        float mean = st * (1.0f / Nn);
        float var  = sst * (1.0f / Nn) - mean * mean;
        float rstd = rsqrtf(var + 1e-5f);
        float w = gw[f], bb = gb[f];
        float sub = mean * gms[0];
        sMul[f] = rstd * w;
        sSub[f] = sub;
        sAdd[f] = bb;
        sSf[f]  = (float)Nn * ((mean - sub) * rstd * w + bb);
    }
    __syncthreads();

    float mul = sMul[f], sub = sSub[f], add = sAdd[f];
#pragma unroll
    for (int n = g * 16; n < g * 16 + 16; n++) {
        float v = (xp[n * FINn] - sub) * mul + add;
        __nv_bfloat16 h, l; split_bf16(v, h, l);
        g_xnh[bt * 4096 + n * 64 + f] = h;
        g_xnl[bt * 4096 + n * 64 + f] = l;
    }

    int o = f;
    float acc = 0.f;
#pragma unroll
    for (int ff = g * 16; ff < g * 16 + 16; ff++)
        acc += sSf[ff] * eb2[ff * FOUTn + o];
    __syncthreads();
    sA[g][o] = acc;
    __syncthreads();
    if (g == 0)
        g_T2[bt * FOUTn + o] = sA[0][o] + sA[1][o] + sA[2][o] + sA[3][o];
}

// ============ K2: GEMM1  P(4096x1024) = xn(4096x64) @ W2(64x1024), mma.sync bf16 ============
// grid (8 n-tiles of 128, 64 m-tiles of 64), 128 threads (4 warps)
#define LDA 88
#define LDB 152
#define G1_SMEM ((2*64*LDA + 2*64*LDB) * 2)   // 61440 bytes
__global__ void __launch_bounds__(128) k_g1() {
    extern __shared__ __align__(16) char ds[];
    __nv_bfloat16* Ah = (__nv_bfloat16*)ds;          // [64][LDA]
    __nv_bfloat16* Al = Ah + 64 * LDA;
    __nv_bfloat16* Bh = Al + 64 * LDA;               // [64 f][LDB] cols = le*64+o
    __nv_bfloat16* Bl = Bh + 64 * LDB;

    int tid = threadIdx.x, warp = tid >> 5, lane = tid & 31;
    int e0 = blockIdx.x * 2;
    int m0 = blockIdx.y * 64;

    // fill A (xn rows m0..m0+63)
#pragma unroll
    for (int l = 0; l < 4; l++) {
        int idx = tid + l * 128;                 // 512 uint4
        int r = idx >> 3, q = idx & 7;
        *(uint4*)(Ah + r * LDA + q * 8) = *(const uint4*)(g_xnh + (m0 + r) * 64 + q * 8);
        *(uint4*)(Al + r * LDA + q * 8) = *(const uint4*)(g_xnl + (m0 + r) * 64 + q * 8);
    }
    // fill B (w2 e0, e0+1)
#pragma unroll
    for (int l = 0; l < 8; l++) {
        int idx = tid + l * 128;                 // 1024 uint4
        int le = idx >> 9, f = (idx >> 3) & 63, q = idx & 7;
        const int src = ((e0 + le) * 64 + f) * 64 + q * 8;
        *(uint4*)(Bh + f * LDB + le * 64 + q * 8) = *(const uint4*)(g_w2h + src);
        *(uint4*)(Bl + f * LDB + le * 64 + q * 8) = *(const uint4*)(g_w2l + src);
    }
    __syncthreads();

    uint32_t aBaseH = smem_u32(Ah), aBaseL = smem_u32(Al);
    uint32_t bBaseH = smem_u32(Bh), bBaseL = smem_u32(Bl);
    int g = lane >> 3, lr = lane & 7;

    // A fragments for all 4 k-steps
    uint32_t ah[16], al[16];
    {
        int arow = warp * 16 + (g & 1) * 8 + lr;
        int acol0 = (g >> 1) * 8;
#pragma unroll
        for (int ks = 0; ks < 4; ks++) {
            uint32_t off = (uint32_t)(arow * LDA + ks * 16 + acol0) * 2;
            LDM_X4(ah[4*ks], ah[4*ks+1], ah[4*ks+2], ah[4*ks+3], aBaseH + off);
            LDM_X4(al[4*ks], al[4*ks+1], al[4*ks+2], al[4*ks+3], aBaseL + off);
        }
    }

    float acc[16][4];
#pragma unroll
    for (int i = 0; i < 16; i++) { acc[i][0]=0.f; acc[i][1]=0.f; acc[i][2]=0.f; acc[i][3]=0.f; }

#pragma unroll
    for (int nt = 0; nt < 16; nt++) {
        uint32_t bh[8], bl[8];
        uint32_t off1 = (uint32_t)((g * 8 + lr) * LDB + nt * 8) * 2;         // k 0..31
        uint32_t off2 = (uint32_t)((32 + g * 8 + lr) * LDB + nt * 8) * 2;    // k 32..63
        LDM_X4T(bh[0], bh[1], bh[2], bh[3], bBaseH + off1);
        LDM_X4T(bh[4], bh[5], bh[6], bh[7], bBaseH + off2);
        LDM_X4T(bl[0], bl[1], bl[2], bl[3], bBaseL + off1);
        LDM_X4T(bl[4], bl[5], bl[6], bl[7], bBaseL + off2);
#pragma unroll
        for (int ks = 0; ks < 4; ks++) {
            mma_bf16(acc[nt], ah + 4*ks, bh[2*ks], bh[2*ks+1]);
            mma_bf16(acc[nt], ah + 4*ks, bl[2*ks], bl[2*ks+1]);
            mma_bf16(acc[nt], al + 4*ks, bh[2*ks], bh[2*ks+1]);
        }
    }

    // store C as bf16 hi/lo into g_Ph/g_Pl
    int r = lane >> 2, c2 = (lane & 3) * 2;
    int gm = m0 + warp * 16 + r;
    int nb0 = blockIdx.x * 128;
#pragma unroll
    for (int nt = 0; nt < 16; nt++) {
        int gn = nb0 + nt * 8 + c2;
#pragma unroll
        for (int half = 0; half < 2; half++) {
            int row = gm + half * 8;
            float v0 = acc[nt][half*2], v1 = acc[nt][half*2+1];
            __nv_bfloat16 h0, l0, h1, l1;
            split_bf16(v0, h0, l0); split_bf16(v1, h1, l1);
            uint32_t ph = ((uint32_t)__bfloat16_as_ushort(h1) << 16) | __bfloat16_as_ushort(h0);
            uint32_t pl = ((uint32_t)__bfloat16_as_ushort(l1) << 16) | __bfloat16_as_ushort(l0);
            *(uint32_t*)(g_Ph + row * EO + gn) = ph;
            *(uint32_t*)(g_Pl + row * EO + gn) = pl;
        }
    }
}

// ============ K3: GEMM2 (agg K-split x4 + node-lin), mma.sync bf16 ============
// blocks 0..255: bt=bid>>2, ks=bid&3; blocks 256..319: node-lin
__global__ void __launch_bounds__(128) k_g2() {
    __shared__ __align__(16) __nv_bfloat16 Hh[64*LDA], Hl[64*LDA];
    __shared__ __align__(16) __nv_bfloat16 Ph[64*LDA], Pl[64*LDA];

    int tid = threadIdx.x, warp = tid >> 5, lane = tid & 31;
    int bid = blockIdx.x;

    const __nv_bfloat16 *AsH, *AsL, *BsH, *BsL;
    float* Cdst;
    int nchunk, strideA;
    if (bid < BT * 4) {
        int bt = bid >> 2, ks = bid & 3, b = bt >> 5;
        AsH = g_hh + b * (Nn * KE) + ks * 256;
        AsL = g_hl + b * (Nn * KE) + ks * 256;
        strideA = KE;
        BsH = g_Ph + bt * 65536 + ks * 256 * 64;
        BsL = g_Pl + bt * 65536 + ks * 256 * 64;
        Cdst = g_part[ks] + bt * (Nn * FOUTn);
        nchunk = 4;
    } else {
        int bt = bid - BT * 4;
        AsH = g_xnh + bt * 4096;
        AsL = g_xnl + bt * 4096;
        strideA = 64;
        BsH = g_nwh;
        BsL = g_nwl;
        Cdst = g_part[4] + bt * (Nn * FOUTn);
        nchunk = 1;
    }

    uint32_t hBaseH = smem_u32(Hh), hBaseL = smem_u32(Hl);
    uint32_t pBaseH = smem_u32(Ph), pBaseL = smem_u32(Pl);
    int g = lane >> 3, lr = lane & 7;
    int arow = warp * 16 + (g & 1) * 8 + lr;
    int acol0 = (g >> 1) * 8;

    float acc[8][4];
#pragma unroll
    for (int i = 0; i < 8; i++) { acc[i][0]=0.f; acc[i][1]=0.f; acc[i][2]=0.f; acc[i][3]=0.f; }

    for (int c = 0; c < nchunk; c++) {
        // fill: A chunk (64 rows x 64 k) + B chunk (64 k-rows x 64 n)
#pragma unroll
        for (int l = 0; l < 4; l++) {
            int idx = tid + l * 128;             // 512 uint4
            int r = idx >> 3, q = idx & 7;
            *(uint4*)(Hh + r * LDA + q * 8) = *(const uint4*)(AsH + r * strideA + c * 64 + q * 8);
            *(uint4*)(Hl + r * LDA + q * 8) = *(const uint4*)(AsL + r * strideA + c * 64 + q * 8);
            *(uint4*)(Ph + r * LDA + q * 8) = *(const uint4*)(BsH + (c * 64 + r) * 64 + q * 8);
            *(uint4*)(Pl + r * LDA + q * 8) = *(const uint4*)(BsL + (c * 64 + r) * 64 + q * 8);
        }
        __syncthreads();

        uint32_t ah[16], al[16];
#pragma unroll
        for (int ks = 0; ks < 4; ks++) {
            uint32_t off = (uint32_t)(arow * LDA + ks * 16 + acol0) * 2;
            LDM_X4(ah[4*ks], ah[4*ks+1], ah[4*ks+2], ah[4*ks+3], hBaseH + off);
            LDM_X4(al[4*ks], al[4*ks+1], al[4*ks+2], al[4*ks+3], hBaseL + off);
        }
#pragma unroll
        for (int nt = 0; nt < 8; nt++) {
            uint32_t bh[8], bl[8];
            uint32_t off1 = (uint32_t)((g * 8 + lr) * LDA + nt * 8) * 2;
            uint32_t off2 = (uint32_t)((32 + g * 8 + lr) * LDA + nt * 8) * 2;
            LDM_X4T(bh[0], bh[1], bh[2], bh[3], pBaseH + off1);
            LDM_X4T(bh[4], bh[5], bh[6], bh[7], pBaseH + off2);
            LDM_X4T(bl[0], bl[1], bl[2], bl[3], pBaseL + off1);
            LDM_X4T(bl[4], bl[5], bl[6], bl[7], pBaseL + off2);
#pragma unroll
            for (int ks = 0; ks < 4; ks++) {
                mma_bf16(acc[nt], ah + 4*ks, bh[2*ks], bh[2*ks+1]);
                mma_bf16(acc[nt], ah + 4*ks, bl[2*ks], bl[2*ks+1]);
                mma_bf16(acc[nt], al + 4*ks, bh[2*ks], bh[2*ks+1]);
            }
        }
        __syncthreads();
    }

    // store fp32 partials
    int r = lane >> 2, c2 = (lane & 3) * 2;
#pragma unroll
    for (int nt = 0; nt < 8; nt++) {
        int col = nt * 8 + c2;
        *(float2*)(Cdst + (warp * 16 + r) * FOUTn + col)     = make_float2(acc[nt][0], acc[nt][1]);
        *(float2*)(Cdst + (warp * 16 + r + 8) * FOUTn + col) = make_float2(acc[nt][2], acc[nt][3]);
    }
}

// ============ K4: elementwise epilogue ============
__global__ void __launch_bounds__(256) k_epi(const float* __restrict__ nb,
                                             float* __restrict__ out) {
    int idx = blockIdx.x * 256 + threadIdx.x;
    int e0 = idx * 4;
    int bt = e0 >> 12;
    int o  = e0 & 63;

    float4 p0 = *(const float4*)(g_part[0] + e0);
    float4 p1 = *(const float4*)(g_part[1] + e0);
    float4 p2 = *(const float4*)(g_part[2] + e0);
    float4 p3 = *(const float4*)(g_part[3] + e0);
    float4 p4 = *(const float4*)(g_part[4] + e0);
    float4 nbv = *(const float4*)(nb + o);
    float4 t2v = *(const float4*)(g_T2 + bt * FOUTn + o);

    float v0 = p0.x + p1.x + p2.x + p3.x + p4.x + nbv.x + t2v.x;
    float v1 = p0.y + p1.y + p2.y + p3.y + p4.y + nbv.y + t2v.y;
    float v2 = p0.z + p1.z + p2.z + p3.z + p4.z + nbv.z + t2v.z;
    float v3 = p0.w + p1.w + p2.w + p3.w + p4.w + nbv.w + t2v.w;
    *(float4*)(out + e0) = make_float4(gelu_exact(v0), gelu_exact(v1),
                                       gelu_exact(v2), gelu_exact(v3));
}

extern "C" void kernel_launch(void* const* d_in, const int* in_sizes, int n_in,
                              void* d_out, int out_size) {
    const float* x   = (const float*)d_in[0];
    const float* adj = (const float*)d_in[1];
    const float* ew1 = (const float*)d_in[2];
    const float* eb1 = (const float*)d_in[3];
    const float* ew2 = (const float*)d_in[4];
    const float* eb2 = (const float*)d_in[5];
    const float* nw  = (const float*)d_in[6];
    const float* nb  = (const float*)d_in[7];
    const float* gw  = (const float*)d_in[8];
    const float* gb  = (const float*)d_in[9];
    const float* gms = (const float*)d_in[10];
    float* out = (float*)d_out;

    static int attr_done = 0;
    if (!attr_done) {
        cudaFuncSetAttribute(k_g1, cudaFuncAttributeMaxDynamicSharedMemorySize, G1_SMEM);
        attr_done = 1;
    }

    k_pre<<<848, 256>>>(x, adj, ew1, eb1, ew2, eb2, nw, gw, gb, gms);
    k_g1<<<dim3(8, 64), 128, G1_SMEM>>>();
    k_g2<<<BT * 4 + BT, 128>>>();
    k_epi<<<(ROWS * FOUTn) / (256 * 4), 256>>>(nb, out);
}

// round 6
// speedup vs baseline: 2.8078x; 1.2427x over previous
#include <cuda_runtime.h>
#include <cuda_bf16.h>
#include <math.h>
#include <stdint.h>

// Problem constants
#define Bn 2
#define Tn 32
#define Nn 64
#define FINn 64
#define FOUTn 64
#define EDIMn 16
#define BT (Bn*Tn)            // 64
#define ROWS (BT*Nn)          // 4096

// -------- device scratch --------
__device__ __nv_bfloat16 g_xnh[ROWS*FINn];        // xn hi  [bt*64+j][f]
__device__ __nv_bfloat16 g_xnl[ROWS*FINn];        // xn lo
__device__ __nv_bfloat16 g_hh[Bn*EDIMn*Nn*Nn];    // h hi   [b][e][i][j]
__device__ __nv_bfloat16 g_hl[Bn*EDIMn*Nn*Nn];
__device__ __nv_bfloat16 g_w2h[EDIMn*FINn*FOUTn]; // ew2 hi [e][f][o]
__device__ __nv_bfloat16 g_w2l[EDIMn*FINn*FOUTn];
__device__ __nv_bfloat16 g_nwh[FINn*FOUTn];       // nw hi [f][o]
__device__ __nv_bfloat16 g_nwl[FINn*FOUTn];
__device__ float g_part[4][BT*Nn*FOUTn];          // per-eg partials (node-lin folded into eg0)
__device__ float g_T2[BT*FOUTn];                  // eb2 contribution

__device__ __forceinline__ float gelu_exact(float v) {
    return 0.5f * v * (1.0f + erff(v * 0.70710678118654752f));
}
__device__ __forceinline__ void split_bf16(float v, __nv_bfloat16& h, __nv_bfloat16& l) {
    h = __float2bfloat16(v);
    l = __float2bfloat16(v - __bfloat162float(h));
}
__device__ __forceinline__ uint32_t smem_u32(const void* p) {
    uint32_t a;
    asm("{ .reg .u64 t; cvta.to.shared.u64 t, %1; cvt.u32.u64 %0, t; }" : "=r"(a) : "l"(p));
    return a;
}

#define LDM_X4(r0,r1,r2,r3,addr) \
    asm volatile("ldmatrix.sync.aligned.m8n8.x4.shared.b16 {%0,%1,%2,%3}, [%4];" \
        : "=r"(r0),"=r"(r1),"=r"(r2),"=r"(r3) : "r"(addr))
#define LDM_X4T(r0,r1,r2,r3,addr) \
    asm volatile("ldmatrix.sync.aligned.m8n8.x4.trans.shared.b16 {%0,%1,%2,%3}, [%4];" \
        : "=r"(r0),"=r"(r1),"=r"(r2),"=r"(r3) : "r"(addr))

__device__ __forceinline__ void mma_bf16(float* c, const uint32_t* a, uint32_t b0, uint32_t b1) {
    asm volatile("mma.sync.aligned.m16n8k16.row.col.f32.bf16.bf16.f32 "
        "{%0,%1,%2,%3}, {%4,%5,%6,%7}, {%8,%9}, {%0,%1,%2,%3};"
        : "+f"(c[0]), "+f"(c[1]), "+f"(c[2]), "+f"(c[3])
        : "r"(a[0]), "r"(a[1]), "r"(a[2]), "r"(a[3]), "r"(b0), "r"(b1));
}

// ============ K1: fused prologue ============
// blk 0..63: norm+T2 | 64..575: edge (h in [b][e][i][j]) | 576..831: ew2 cvt | 832..847: nw cvt
__global__ void __launch_bounds__(256) k_pre(const float* __restrict__ x,
                                             const float* __restrict__ adj,
                                             const float* __restrict__ ew1,
                                             const float* __restrict__ eb1,
                                             const float* __restrict__ ew2,
                                             const float* __restrict__ eb2,
                                             const float* __restrict__ nw,
                                             const float* __restrict__ gw,
                                             const float* __restrict__ gb,
                                             const float* __restrict__ gms) {
    int blk = blockIdx.x;
    int tid = threadIdx.x;

    if (blk >= 832) {                       // nw convert
        int idx = (blk - 832) * 256 + tid;
        __nv_bfloat16 h, l; split_bf16(nw[idx], h, l);
        g_nwh[idx] = h; g_nwl[idx] = l;
        return;
    }
    if (blk >= 576) {                       // ew2 convert
        int idx = (blk - 576) * 256 + tid;
        __nv_bfloat16 h, l; split_bf16(ew2[idx], h, l);
        g_w2h[idx] = h; g_w2l[idx] = l;
        return;
    }
    if (blk >= BT) {                        // edge: h[b][e][i][j]
        int row = (blk - BT) * 4 + (tid >> 6);   // (b,e,i): 2048 rows
        int j = tid & 63;
        int b = row >> 10, e = (row >> 6) & 15, i = row & 63;
        float a = adj[b * 4096 + i * 64 + j];
        float v = gelu_exact(a * ew1[e] + eb1[e]);
        __nv_bfloat16 h, l; split_bf16(v, h, l);
        g_hh[row * 64 + j] = h;
        g_hl[row * 64 + j] = l;
        return;
    }

    // ---- norm + T2 ----
    int bt = blk;
    int f = tid & 63;
    int g = tid >> 6;
    __shared__ float sA[4][64];
    __shared__ float sB[4][64];
    __shared__ float sMul[64], sSub[64], sAdd[64], sSf[64];

    const float* xp = x + bt * (Nn * FINn) + f;
    float s = 0.f, ss = 0.f;
#pragma unroll
    for (int n = g * 16; n < g * 16 + 16; n++) {
        float v = xp[n * FINn];
        s += v; ss += v * v;
    }
    sA[g][f] = s; sB[g][f] = ss;
    __syncthreads();

    if (g == 0) {
        float st  = sA[0][f] + sA[1][f] + sA[2][f] + sA[3][f];
        float sst = sB[0][f] + sB[1][f] + sB[2][f] + sB[3][f];
        float mean = st * (1.0f / Nn);
        float var  = sst * (1.0f / Nn) - mean * mean;
        float rstd = rsqrtf(var + 1e-5f);
        float w = gw[f], bb = gb[f];
        float sub = mean * gms[0];
        sMul[f] = rstd * w;
        sSub[f] = sub;
        sAdd[f] = bb;
        sSf[f]  = (float)Nn * ((mean - sub) * rstd * w + bb);
    }
    __syncthreads();

    float mul = sMul[f], sub = sSub[f], add = sAdd[f];
#pragma unroll
    for (int n = g * 16; n < g * 16 + 16; n++) {
        float v = (xp[n * FINn] - sub) * mul + add;
        __nv_bfloat16 h, l; split_bf16(v, h, l);
        g_xnh[bt * 4096 + n * 64 + f] = h;
        g_xnl[bt * 4096 + n * 64 + f] = l;
    }

    int o = f;
    float acc = 0.f;
#pragma unroll
    for (int ff = g * 16; ff < g * 16 + 16; ff++)
        acc += sSf[ff] * eb2[ff * FOUTn + o];
    __syncthreads();
    sA[g][o] = acc;
    __syncthreads();
    if (g == 0)
        g_T2[bt * FOUTn + o] = sA[0][o] + sA[1][o] + sA[2][o] + sA[3][o];
}

// ============ K2: fused GEMM  (P_e in smem, never gmem) ============
// block = (bt, eg):  for e in eg*4..+3:  Ps = xn_bt @ W2_e ; agg += h_be @ Ps
// eg==0 additionally: agg += xn_bt @ nw.   Writes g_part[eg].
#define LDA 88
#define TILE (64*LDA)
#define FUS_SMEM (8*TILE*2)     // 90112 bytes

__global__ void __launch_bounds__(128) k_fused() {
    extern __shared__ __align__(16) __nv_bfloat16 ds[];
    __nv_bfloat16 *Xh = ds,          *Xl = ds + TILE;
    __nv_bfloat16 *Wh = ds + 2*TILE, *Wl = ds + 3*TILE;
    __nv_bfloat16 *Hh = ds + 4*TILE, *Hl = ds + 5*TILE;
    __nv_bfloat16 *Ph = ds + 6*TILE, *Pl = ds + 7*TILE;

    int tid = threadIdx.x, warp = tid >> 5, lane = tid & 31;
    int bt = blockIdx.x >> 2, eg = blockIdx.x & 3;
    int b = bt >> 5;

    // ---- load xn tile (persistent) ----
#pragma unroll
    for (int l = 0; l < 4; l++) {
        int idx = tid + l * 128;             // 512 uint4
        int r = idx >> 3, q = idx & 7;
        *(uint4*)(Xh + r * LDA + q * 8) = *(const uint4*)(g_xnh + bt * 4096 + r * 64 + q * 8);
        *(uint4*)(Xl + r * LDA + q * 8) = *(const uint4*)(g_xnl + bt * 4096 + r * 64 + q * 8);
    }
    __syncthreads();

    uint32_t xBh = smem_u32(Xh), xBl = smem_u32(Xl);
    uint32_t wBh = smem_u32(Wh), wBl = smem_u32(Wl);
    uint32_t hBh = smem_u32(Hh), hBl = smem_u32(Hl);
    uint32_t pBh = smem_u32(Ph), pBl = smem_u32(Pl);

    int g = lane >> 3, lr = lane & 7;
    int arow = warp * 16 + (g & 1) * 8 + lr;
    int acol0 = (g >> 1) * 8;

    // xn A-fragments (rows act as j for mma1, as i for node-lin)
    uint32_t xh[16], xl[16];
#pragma unroll
    for (int ks = 0; ks < 4; ks++) {
        uint32_t off = (uint32_t)(arow * LDA + ks * 16 + acol0) * 2;
        LDM_X4(xh[4*ks], xh[4*ks+1], xh[4*ks+2], xh[4*ks+3], xBh + off);
        LDM_X4(xl[4*ks], xl[4*ks+1], xl[4*ks+2], xl[4*ks+3], xBl + off);
    }

    float agg[8][4];
#pragma unroll
    for (int i = 0; i < 8; i++) { agg[i][0]=0.f; agg[i][1]=0.f; agg[i][2]=0.f; agg[i][3]=0.f; }

    int cr = lane >> 2, cc2 = (lane & 3) * 2;

    for (int ee = 0; ee < 4; ee++) {
        int e = eg * 4 + ee;
        // load W2_e and h_(b,e)
        const __nv_bfloat16* w2hp = g_w2h + e * 4096;
        const __nv_bfloat16* w2lp = g_w2l + e * 4096;
        const __nv_bfloat16* hhp  = g_hh + (b * 16 + e) * 4096;
        const __nv_bfloat16* hlp  = g_hl + (b * 16 + e) * 4096;
#pragma unroll
        for (int l = 0; l < 4; l++) {
            int idx = tid + l * 128;
            int r = idx >> 3, q = idx & 7;
            *(uint4*)(Wh + r * LDA + q * 8) = *(const uint4*)(w2hp + r * 64 + q * 8);
            *(uint4*)(Wl + r * LDA + q * 8) = *(const uint4*)(w2lp + r * 64 + q * 8);
            *(uint4*)(Hh + r * LDA + q * 8) = *(const uint4*)(hhp + r * 64 + q * 8);
            *(uint4*)(Hl + r * LDA + q * 8) = *(const uint4*)(hlp + r * 64 + q * 8);
        }
        __syncthreads();

        // ---- mma1: Ps = xn @ W2_e  (per nt: compute + split + store) ----
#pragma unroll
        for (int nt = 0; nt < 8; nt++) {
            float pacc[4] = {0.f, 0.f, 0.f, 0.f};
            uint32_t bh[8], bl[8];
            uint32_t off1 = (uint32_t)((g * 8 + lr) * LDA + nt * 8) * 2;
            uint32_t off2 = (uint32_t)((32 + g * 8 + lr) * LDA + nt * 8) * 2;
            LDM_X4T(bh[0], bh[1], bh[2], bh[3], wBh + off1);
            LDM_X4T(bh[4], bh[5], bh[6], bh[7], wBh + off2);
            LDM_X4T(bl[0], bl[1], bl[2], bl[3], wBl + off1);
            LDM_X4T(bl[4], bl[5], bl[6], bl[7], wBl + off2);
#pragma unroll
            for (int ks = 0; ks < 4; ks++) {
                mma_bf16(pacc, xh + 4*ks, bh[2*ks], bh[2*ks+1]);
                mma_bf16(pacc, xh + 4*ks, bl[2*ks], bl[2*ks+1]);
                mma_bf16(pacc, xl + 4*ks, bh[2*ks], bh[2*ks+1]);
            }
            // split + store to Ps
#pragma unroll
            for (int half = 0; half < 2; half++) {
                int row = warp * 16 + cr + half * 8;
                int col = nt * 8 + cc2;
                __nv_bfloat16 h0, l0, h1, l1;
                split_bf16(pacc[half*2], h0, l0);
                split_bf16(pacc[half*2+1], h1, l1);
                *(uint32_t*)(Ph + row * LDA + col) =
                    ((uint32_t)__bfloat16_as_ushort(h1) << 16) | __bfloat16_as_ushort(h0);
                *(uint32_t*)(Pl + row * LDA + col) =
                    ((uint32_t)__bfloat16_as_ushort(l1) << 16) | __bfloat16_as_ushort(l0);
            }
        }
        __syncthreads();

        // ---- mma2: agg += h_e @ Ps ----
        uint32_t ahh[16], ahl[16];
#pragma unroll
        for (int ks = 0; ks < 4; ks++) {
            uint32_t off = (uint32_t)(arow * LDA + ks * 16 + acol0) * 2;
            LDM_X4(ahh[4*ks], ahh[4*ks+1], ahh[4*ks+2], ahh[4*ks+3], hBh + off);
            LDM_X4(ahl[4*ks], ahl[4*ks+1], ahl[4*ks+2], ahl[4*ks+3], hBl + off);
        }
#pragma unroll
        for (int nt = 0; nt < 8; nt++) {
            uint32_t bh[8], bl[8];
            uint32_t off1 = (uint32_t)((g * 8 + lr) * LDA + nt * 8) * 2;
            uint32_t off2 = (uint32_t)((32 + g * 8 + lr) * LDA + nt * 8) * 2;
            LDM_X4T(bh[0], bh[1], bh[2], bh[3], pBh + off1);
            LDM_X4T(bh[4], bh[5], bh[6], bh[7], pBh + off2);
            LDM_X4T(bl[0], bl[1], bl[2], bl[3], pBl + off1);
            LDM_X4T(bl[4], bl[5], bl[6], bl[7], pBl + off2);
#pragma unroll
            for (int ks = 0; ks < 4; ks++) {
                mma_bf16(agg[nt], ahh + 4*ks, bh[2*ks], bh[2*ks+1]);
                mma_bf16(agg[nt], ahh + 4*ks, bl[2*ks], bl[2*ks+1]);
                mma_bf16(agg[nt], ahl + 4*ks, bh[2*ks], bh[2*ks+1]);
            }
        }
        __syncthreads();
    }

    // ---- eg 0: node-lin  agg += xn @ nw (xn frags already in regs) ----
    if (eg == 0) {
#pragma unroll
        for (int l = 0; l < 4; l++) {
            int idx = tid + l * 128;
            int r = idx >> 3, q = idx & 7;
            *(uint4*)(Wh + r * LDA + q * 8) = *(const uint4*)(g_nwh + r * 64 + q * 8);
            *(uint4*)(Wl + r * LDA + q * 8) = *(const uint4*)(g_nwl + r * 64 + q * 8);
        }
        __syncthreads();
#pragma unroll
        for (int nt = 0; nt < 8; nt++) {
            uint32_t bh[8], bl[8];
            uint32_t off1 = (uint32_t)((g * 8 + lr) * LDA + nt * 8) * 2;
            uint32_t off2 = (uint32_t)((32 + g * 8 + lr) * LDA + nt * 8) * 2;
            LDM_X4T(bh[0], bh[1], bh[2], bh[3], wBh + off1);
            LDM_X4T(bh[4], bh[5], bh[6], bh[7], wBh + off2);
            LDM_X4T(bl[0], bl[1], bl[2], bl[3], wBl + off1);
            LDM_X4T(bl[4], bl[5], bl[6], bl[7], wBl + off2);
#pragma unroll
            for (int ks = 0; ks < 4; ks++) {
                mma_bf16(agg[nt], xh + 4*ks, bh[2*ks], bh[2*ks+1]);
                mma_bf16(agg[nt], xh + 4*ks, bl[2*ks], bl[2*ks+1]);
                mma_bf16(agg[nt], xl + 4*ks, bh[2*ks], bh[2*ks+1]);
            }
        }
    }

    // ---- store partial ----
    float* Cdst = g_part[eg] + bt * (Nn * FOUTn);
#pragma unroll
    for (int nt = 0; nt < 8; nt++) {
        int col = nt * 8 + cc2;
        *(float2*)(Cdst + (warp * 16 + cr) * FOUTn + col)     = make_float2(agg[nt][0], agg[nt][1]);
        *(float2*)(Cdst + (warp * 16 + cr + 8) * FOUTn + col) = make_float2(agg[nt][2], agg[nt][3]);
    }
}

// ============ K3: elementwise epilogue ============
__global__ void __launch_bounds__(256) k_epi(const float* __restrict__ nb,
                                             float* __restrict__ out) {
    int idx = blockIdx.x * 256 + threadIdx.x;
    int e0 = idx * 4;
    int bt = e0 >> 12;
    int o  = e0 & 63;

    float4 p0 = *(const float4*)(g_part[0] + e0);
    float4 p1 = *(const float4*)(g_part[1] + e0);
    float4 p2 = *(const float4*)(g_part[2] + e0);
    float4 p3 = *(const float4*)(g_part[3] + e0);
    float4 nbv = *(const float4*)(nb + o);
    float4 t2v = *(const float4*)(g_T2 + bt * FOUTn + o);

    float v0 = p0.x + p1.x + p2.x + p3.x + nbv.x + t2v.x;
    float v1 = p0.y + p1.y + p2.y + p3.y + nbv.y + t2v.y;
    float v2 = p0.z + p1.z + p2.z + p3.z + nbv.z + t2v.z;
    float v3 = p0.w + p1.w + p2.w + p3.w + nbv.w + t2v.w;
    *(float4*)(out + e0) = make_float4(gelu_exact(v0), gelu_exact(v1),
                                       gelu_exact(v2), gelu_exact(v3));
}

extern "C" void kernel_launch(void* const* d_in, const int* in_sizes, int n_in,
                              void* d_out, int out_size) {
    const float* x   = (const float*)d_in[0];
    const float* adj = (const float*)d_in[1];
    const float* ew1 = (const float*)d_in[2];
    const float* eb1 = (const float*)d_in[3];
    const float* ew2 = (const float*)d_in[4];
    const float* eb2 = (const float*)d_in[5];
    const float* nw  = (const float*)d_in[6];
    const float* nb  = (const float*)d_in[7];
    const float* gw  = (const float*)d_in[8];
    const float* gb  = (const float*)d_in[9];
    const float* gms = (const float*)d_in[10];
    float* out = (float*)d_out;

    cudaFuncSetAttribute(k_fused, cudaFuncAttributeMaxDynamicSharedMemorySize, FUS_SMEM);

    k_pre<<<848, 256>>>(x, adj, ew1, eb1, ew2, eb2, nw, gw, gb, gms);
    k_fused<<<BT * 4, 128, FUS_SMEM>>>();
    k_epi<<<(ROWS * FOUTn) / (256 * 4), 256>>>(nb, out);
}

// round 7
// speedup vs baseline: 2.8365x; 1.0102x over previous
#include <cuda_runtime.h>
#include <cuda_bf16.h>
#include <math.h>
#include <stdint.h>

// Problem constants
#define Bn 2
#define Tn 32
#define Nn 64
#define FINn 64
#define FOUTn 64
#define EDIMn 16
#define BT (Bn*Tn)            // 64
#define ROWS (BT*Nn)          // 4096
#define NBLK 256              // grid size; all must be co-resident (2/SM * 148 = 296 >= 256)

// -------- device scratch --------
__device__ __nv_bfloat16 g_xnh[ROWS*FINn];        // xn hi  [bt*64+j][f]
__device__ __nv_bfloat16 g_xnl[ROWS*FINn];        // xn lo
__device__ __nv_bfloat16 g_hh[Bn*EDIMn*Nn*Nn];    // h hi   [b][e][i][j]
__device__ __nv_bfloat16 g_hl[Bn*EDIMn*Nn*Nn];
__device__ __nv_bfloat16 g_w2h[EDIMn*FINn*FOUTn]; // ew2 hi [e][f][o]
__device__ __nv_bfloat16 g_w2l[EDIMn*FINn*FOUTn];
__device__ __nv_bfloat16 g_nwh[FINn*FOUTn];       // nw hi [f][o]
__device__ __nv_bfloat16 g_nwl[FINn*FOUTn];
__device__ float g_part[4][BT*Nn*FOUTn];          // per-eg partials (node-lin in eg0)
__device__ float g_T2[BT*FOUTn];                  // eb2 contribution
__device__ unsigned g_bcnt;                       // global barrier counter (returns to 0 each run)

__device__ __forceinline__ float gelu_exact(float v) {
    return 0.5f * v * (1.0f + erff(v * 0.70710678118654752f));
}
__device__ __forceinline__ void split_bf16(float v, __nv_bfloat16& h, __nv_bfloat16& l) {
    h = __float2bfloat16(v);
    l = __float2bfloat16(v - __bfloat162float(h));
}
__device__ __forceinline__ uint32_t smem_u32(const void* p) {
    uint32_t a;
    asm("{ .reg .u64 t; cvta.to.shared.u64 t, %1; cvt.u32.u64 %0, t; }" : "=r"(a) : "l"(p));
    return a;
}

#define LDM_X4(r0,r1,r2,r3,addr) \
    asm volatile("ldmatrix.sync.aligned.m8n8.x4.shared.b16 {%0,%1,%2,%3}, [%4];" \
        : "=r"(r0),"=r"(r1),"=r"(r2),"=r"(r3) : "r"(addr))
#define LDM_X4T(r0,r1,r2,r3,addr) \
    asm volatile("ldmatrix.sync.aligned.m8n8.x4.trans.shared.b16 {%0,%1,%2,%3}, [%4];" \
        : "=r"(r0),"=r"(r1),"=r"(r2),"=r"(r3) : "r"(addr))

__device__ __forceinline__ void mma_bf16(float* c, const uint32_t* a, uint32_t b0, uint32_t b1) {
    asm volatile("mma.sync.aligned.m16n8k16.row.col.f32.bf16.bf16.f32 "
        "{%0,%1,%2,%3}, {%4,%5,%6,%7}, {%8,%9}, {%0,%1,%2,%3};"
        : "+f"(c[0]), "+f"(c[1]), "+f"(c[2]), "+f"(c[3])
        : "r"(a[0]), "r"(a[1]), "r"(a[2]), "r"(a[3]), "r"(b0), "r"(b1));
}

// Global barrier: atomicInc with limit 2*NBLK-1. Counter path per run:
//   barrier1 arrivals -> 1..256 (release when >= NBLK)
//   barrier2 arrivals -> 257..511, then last wraps to 0 (release when == 0)
// Ends at 0: safe across graph replays. Wrap cannot occur while any block
// still spins at barrier1 (its own 2nd arrival is required for the wrap).
__device__ __forceinline__ void gbar(int which) {
    __syncthreads();
    if (threadIdx.x == 0) {
        __threadfence();
        atomicInc(&g_bcnt, 2u * NBLK - 1u);
        volatile unsigned* p = &g_bcnt;
        if (which == 1) { while (*p < NBLK && *p != 0u) {} }
        else           { while (*p != 0u) {} }
        __threadfence();
    }
    __syncthreads();
}

// Fused-GEMM smem geometry
#define LDA 72
#define TILE (64*LDA)                  // 4608 bf16
#define FUS_SMEM (8*TILE*2)            // 73728 bytes -> 2 CTAs/SM guaranteed

__global__ void __launch_bounds__(128, 2)
k_all(const float* __restrict__ x,   const float* __restrict__ adj,
      const float* __restrict__ ew1, const float* __restrict__ eb1,
      const float* __restrict__ ew2, const float* __restrict__ eb2,
      const float* __restrict__ nw,  const float* __restrict__ nb,
      const float* __restrict__ gw,  const float* __restrict__ gb,
      const float* __restrict__ gms, float* __restrict__ out) {
    extern __shared__ __align__(16) __nv_bfloat16 ds[];
    int tid = threadIdx.x, blk = blockIdx.x;

    // =================== PHASE A: prologue ===================
    if (blk < BT) {
        // ---- norm + T2 for bt = blk (128 threads: 2 groups x 64 features) ----
        int bt = blk;
        int f = tid & 63;
        int g = tid >> 6;                       // 0..1, 32 rows each
        float* sA   = (float*)ds;               // [2][64]
        float* sB   = sA + 128;                 // [2][64]
        float* sMul = sB + 128;
        float* sSub = sMul + 64;
        float* sAdd = sSub + 64;
        float* sSf  = sAdd + 64;

        const float* xp = x + bt * (Nn * FINn) + f;
        float s = 0.f, ss = 0.f;
#pragma unroll
        for (int n = g * 32; n < g * 32 + 32; n++) {
            float v = xp[n * FINn];
            s += v; ss += v * v;
        }
        sA[g * 64 + f] = s; sB[g * 64 + f] = ss;
        __syncthreads();

        if (g == 0) {
            float st  = sA[f] + sA[64 + f];
            float sst = sB[f] + sB[64 + f];
            float mean = st * (1.0f / Nn);
            float var  = sst * (1.0f / Nn) - mean * mean;
            float rstd = rsqrtf(var + 1e-5f);
            float w = gw[f], bbv = gb[f];
            float sub = mean * gms[0];
            sMul[f] = rstd * w;
            sSub[f] = sub;
            sAdd[f] = bbv;
            sSf[f]  = (float)Nn * ((mean - sub) * rstd * w + bbv);
        }
        __syncthreads();

        float mul = sMul[f], sub = sSub[f], add = sAdd[f];
#pragma unroll
        for (int n = g * 32; n < g * 32 + 32; n++) {
            float v = (xp[n * FINn] - sub) * mul + add;
            __nv_bfloat16 h, l; split_bf16(v, h, l);
            g_xnh[bt * 4096 + n * 64 + f] = h;
            g_xnl[bt * 4096 + n * 64 + f] = l;
        }

        int o = f;
        float acc = 0.f;
#pragma unroll
        for (int ff = g * 32; ff < g * 32 + 32; ff++)
            acc += sSf[ff] * eb2[ff * FOUTn + o];
        __syncthreads();
        sA[g * 64 + o] = acc;
        __syncthreads();
        if (g == 0)
            g_T2[bt * FOUTn + o] = sA[o] + sA[64 + o];
        __syncthreads();
    } else if (blk < BT + 32) {
        // ---- nw convert: 4096 elems over blocks 64..95 ----
        int idx = (blk - BT) * 128 + tid;
        __nv_bfloat16 h, l; split_bf16(nw[idx], h, l);
        g_nwh[idx] = h; g_nwl[idx] = l;
    }

    // ---- edge (all blocks): h[b][e][i][j], 2048 rows, 8 rows/block ----
    {
        int row = blk * 8 + (tid >> 4);         // (b,e,i)
        int j4 = (tid & 15) * 4;
        int b = row >> 10, e = (row >> 6) & 15, i = row & 63;
        float4 a4 = *(const float4*)(adj + b * 4096 + i * 64 + j4);
        float w1 = ew1[e], b1 = eb1[e];
        __nv_bfloat16 h0,l0,h1,l1,h2,l2,h3,l3;
        split_bf16(gelu_exact(a4.x * w1 + b1), h0, l0);
        split_bf16(gelu_exact(a4.y * w1 + b1), h1, l1);
        split_bf16(gelu_exact(a4.z * w1 + b1), h2, l2);
        split_bf16(gelu_exact(a4.w * w1 + b1), h3, l3);
        uint32_t ph0 = ((uint32_t)__bfloat16_as_ushort(h1) << 16) | __bfloat16_as_ushort(h0);
        uint32_t ph1 = ((uint32_t)__bfloat16_as_ushort(h3) << 16) | __bfloat16_as_ushort(h2);
        uint32_t pl0 = ((uint32_t)__bfloat16_as_ushort(l1) << 16) | __bfloat16_as_ushort(l0);
        uint32_t pl1 = ((uint32_t)__bfloat16_as_ushort(l3) << 16) | __bfloat16_as_ushort(l2);
        *(uint2*)(g_hh + row * 64 + j4) = make_uint2(ph0, ph1);
        *(uint2*)(g_hl + row * 64 + j4) = make_uint2(pl0, pl1);
    }
    // ---- ew2 convert (all blocks): 65536 elems, 256/block ----
    {
        int idx = blk * 256 + tid * 2;
        float2 v = *(const float2*)(ew2 + idx);
        __nv_bfloat16 h0,l0,h1,l1;
        split_bf16(v.x, h0, l0); split_bf16(v.y, h1, l1);
        *(uint32_t*)(g_w2h + idx) = ((uint32_t)__bfloat16_as_ushort(h1) << 16) | __bfloat16_as_ushort(h0);
        *(uint32_t*)(g_w2l + idx) = ((uint32_t)__bfloat16_as_ushort(l1) << 16) | __bfloat16_as_ushort(l0);
    }

    gbar(1);

    // =================== PHASE B: fused GEMM ===================
    {
        __nv_bfloat16 *Xh = ds,          *Xl = ds + TILE;
        __nv_bfloat16 *Wh = ds + 2*TILE, *Wl = ds + 3*TILE;
        __nv_bfloat16 *Hh = ds + 4*TILE, *Hl = ds + 5*TILE;
        __nv_bfloat16 *Ph = ds + 6*TILE, *Pl = ds + 7*TILE;

        int warp = tid >> 5, lane = tid & 31;
        int bt = blk >> 2, eg = blk & 3;
        int b = bt >> 5;

        __syncthreads();   // phase A smem overlay fully consumed (gbar synced anyway)

#pragma unroll
        for (int l = 0; l < 4; l++) {
            int idx = tid + l * 128;             // 512 uint4
            int r = idx >> 3, q = idx & 7;
            *(uint4*)(Xh + r * LDA + q * 8) = *(const uint4*)(g_xnh + bt * 4096 + r * 64 + q * 8);
            *(uint4*)(Xl + r * LDA + q * 8) = *(const uint4*)(g_xnl + bt * 4096 + r * 64 + q * 8);
        }
        __syncthreads();

        uint32_t xBh = smem_u32(Xh), xBl = smem_u32(Xl);
        uint32_t wBh = smem_u32(Wh), wBl = smem_u32(Wl);
        uint32_t hBh = smem_u32(Hh), hBl = smem_u32(Hl);
        uint32_t pBh = smem_u32(Ph), pBl = smem_u32(Pl);

        int g = lane >> 3, lr = lane & 7;
        int arow = warp * 16 + (g & 1) * 8 + lr;
        int acol0 = (g >> 1) * 8;

        uint32_t xh[16], xl[16];
#pragma unroll
        for (int ks = 0; ks < 4; ks++) {
            uint32_t off = (uint32_t)(arow * LDA + ks * 16 + acol0) * 2;
            LDM_X4(xh[4*ks], xh[4*ks+1], xh[4*ks+2], xh[4*ks+3], xBh + off);
            LDM_X4(xl[4*ks], xl[4*ks+1], xl[4*ks+2], xl[4*ks+3], xBl + off);
        }

        float agg[8][4];
#pragma unroll
        for (int i = 0; i < 8; i++) { agg[i][0]=0.f; agg[i][1]=0.f; agg[i][2]=0.f; agg[i][3]=0.f; }

        int cr = lane >> 2, cc2 = (lane & 3) * 2;

        for (int ee = 0; ee < 4; ee++) {
            int e = eg * 4 + ee;
            const __nv_bfloat16* w2hp = g_w2h + e * 4096;
            const __nv_bfloat16* w2lp = g_w2l + e * 4096;
            const __nv_bfloat16* hhp  = g_hh + (b * 16 + e) * 4096;
            const __nv_bfloat16* hlp  = g_hl + (b * 16 + e) * 4096;
#pragma unroll
            for (int l = 0; l < 4; l++) {
                int idx = tid + l * 128;
                int r = idx >> 3, q = idx & 7;
                *(uint4*)(Wh + r * LDA + q * 8) = *(const uint4*)(w2hp + r * 64 + q * 8);
                *(uint4*)(Wl + r * LDA + q * 8) = *(const uint4*)(w2lp + r * 64 + q * 8);
                *(uint4*)(Hh + r * LDA + q * 8) = *(const uint4*)(hhp + r * 64 + q * 8);
                *(uint4*)(Hl + r * LDA + q * 8) = *(const uint4*)(hlp + r * 64 + q * 8);
            }
            __syncthreads();

            // ---- mma1: Ps = xn @ W2_e ----
#pragma unroll
            for (int nt = 0; nt < 8; nt++) {
                float pacc[4] = {0.f, 0.f, 0.f, 0.f};
                uint32_t bh[8], bl[8];
                uint32_t off1 = (uint32_t)((g * 8 + lr) * LDA + nt * 8) * 2;
                uint32_t off2 = (uint32_t)((32 + g * 8 + lr) * LDA + nt * 8) * 2;
                LDM_X4T(bh[0], bh[1], bh[2], bh[3], wBh + off1);
                LDM_X4T(bh[4], bh[5], bh[6], bh[7], wBh + off2);
                LDM_X4T(bl[0], bl[1], bl[2], bl[3], wBl + off1);
                LDM_X4T(bl[4], bl[5], bl[6], bl[7], wBl + off2);
#pragma unroll
                for (int ks = 0; ks < 4; ks++) {
                    mma_bf16(pacc, xh + 4*ks, bh[2*ks], bh[2*ks+1]);
                    mma_bf16(pacc, xh + 4*ks, bl[2*ks], bl[2*ks+1]);
                    mma_bf16(pacc, xl + 4*ks, bh[2*ks], bh[2*ks+1]);
                }
#pragma unroll
                for (int half = 0; half < 2; half++) {
                    int row = warp * 16 + cr + half * 8;
                    int col = nt * 8 + cc2;
                    __nv_bfloat16 h0, l0, h1, l1;
                    split_bf16(pacc[half*2], h0, l0);
                    split_bf16(pacc[half*2+1], h1, l1);
                    *(uint32_t*)(Ph + row * LDA + col) =
                        ((uint32_t)__bfloat16_as_ushort(h1) << 16) | __bfloat16_as_ushort(h0);
                    *(uint32_t*)(Pl + row * LDA + col) =
                        ((uint32_t)__bfloat16_as_ushort(l1) << 16) | __bfloat16_as_ushort(l0);
                }
            }
            __syncthreads();

            // ---- mma2: agg += h_e @ Ps ----
            uint32_t ahh[16], ahl[16];
#pragma unroll
            for (int ks = 0; ks < 4; ks++) {
                uint32_t off = (uint32_t)(arow * LDA + ks * 16 + acol0) * 2;
                LDM_X4(ahh[4*ks], ahh[4*ks+1], ahh[4*ks+2], ahh[4*ks+3], hBh + off);
                LDM_X4(ahl[4*ks], ahl[4*ks+1], ahl[4*ks+2], ahl[4*ks+3], hBl + off);
            }
#pragma unroll
            for (int nt = 0; nt < 8; nt++) {
                uint32_t bh[8], bl[8];
                uint32_t off1 = (uint32_t)((g * 8 + lr) * LDA + nt * 8) * 2;
                uint32_t off2 = (uint32_t)((32 + g * 8 + lr) * LDA + nt * 8) * 2;
                LDM_X4T(bh[0], bh[1], bh[2], bh[3], pBh + off1);
                LDM_X4T(bh[4], bh[5], bh[6], bh[7], pBh + off2);
                LDM_X4T(bl[0], bl[1], bl[2], bl[3], pBl + off1);
                LDM_X4T(bl[4], bl[5], bl[6], bl[7], pBl + off2);
#pragma unroll
                for (int ks = 0; ks < 4; ks++) {
                    mma_bf16(agg[nt], ahh + 4*ks, bh[2*ks], bh[2*ks+1]);
                    mma_bf16(agg[nt], ahh + 4*ks, bl[2*ks], bl[2*ks+1]);
                    mma_bf16(agg[nt], ahl + 4*ks, bh[2*ks], bh[2*ks+1]);
                }
            }
            __syncthreads();
        }

        // ---- eg 0: node-lin agg += xn @ nw ----
        if (eg == 0) {
#pragma unroll
            for (int l = 0; l < 4; l++) {
                int idx = tid + l * 128;
                int r = idx >> 3, q = idx & 7;
                *(uint4*)(Wh + r * LDA + q * 8) = *(const uint4*)(g_nwh + r * 64 + q * 8);
                *(uint4*)(Wl + r * LDA + q * 8) = *(const uint4*)(g_nwl + r * 64 + q * 8);
            }
            __syncthreads();
#pragma unroll
            for (int nt = 0; nt < 8; nt++) {
                uint32_t bh[8], bl[8];
                uint32_t off1 = (uint32_t)((g * 8 + lr) * LDA + nt * 8) * 2;
                uint32_t off2 = (uint32_t)((32 + g * 8 + lr) * LDA + nt * 8) * 2;
                LDM_X4T(bh[0], bh[1], bh[2], bh[3], wBh + off1);
                LDM_X4T(bh[4], bh[5], bh[6], bh[7], wBh + off2);
                LDM_X4T(bl[0], bl[1], bl[2], bl[3], wBl + off1);
                LDM_X4T(bl[4], bl[5], bl[6], bl[7], wBl + off2);
#pragma unroll
                for (int ks = 0; ks < 4; ks++) {
                    mma_bf16(agg[nt], xh + 4*ks, bh[2*ks], bh[2*ks+1]);
                    mma_bf16(agg[nt], xh + 4*ks, bl[2*ks], bl[2*ks+1]);
                    mma_bf16(agg[nt], xl + 4*ks, bh[2*ks], bh[2*ks+1]);
                }
            }
        }

        float* Cdst = g_part[eg] + bt * (Nn * FOUTn);
#pragma unroll
        for (int nt = 0; nt < 8; nt++) {
            int col = nt * 8 + cc2;
            *(float2*)(Cdst + (warp * 16 + cr) * FOUTn + col)     = make_float2(agg[nt][0], agg[nt][1]);
            *(float2*)(Cdst + (warp * 16 + cr + 8) * FOUTn + col) = make_float2(agg[nt][2], agg[nt][3]);
        }
    }

    gbar(2);

    // =================== PHASE C: epilogue ===================
#pragma unroll
    for (int k = 0; k < 2; k++) {
        int idx = blk * 256 + tid * 2 + k;       // 65536 float4 tasks
        int e0 = idx * 4;
        int bt = e0 >> 12;
        int o  = e0 & 63;

        float4 p0 = *(const float4*)(g_part[0] + e0);
        float4 p1 = *(const float4*)(g_part[1] + e0);
        float4 p2 = *(const float4*)(g_part[2] + e0);
        float4 p3 = *(const float4*)(g_part[3] + e0);
        float4 nbv = *(const float4*)(nb + o);
        float4 t2v = *(const float4*)(g_T2 + bt * FOUTn + o);

        float v0 = p0.x + p1.x + p2.x + p3.x + nbv.x + t2v.x;
        float v1 = p0.y + p1.y + p2.y + p3.y + nbv.y + t2v.y;
        float v2 = p0.z + p1.z + p2.z + p3.z + nbv.z + t2v.z;
        float v3 = p0.w + p1.w + p2.w + p3.w + nbv.w + t2v.w;
        *(float4*)(out + e0) = make_float4(gelu_exact(v0), gelu_exact(v1),
                                           gelu_exact(v2), gelu_exact(v3));
    }
}

extern "C" void kernel_launch(void* const* d_in, const int* in_sizes, int n_in,
                              void* d_out, int out_size) {
    const float* x   = (const float*)d_in[0];
    const float* adj = (const float*)d_in[1];
    const float* ew1 = (const float*)d_in[2];
    const float* eb1 = (const float*)d_in[3];
    const float* ew2 = (const float*)d_in[4];
    const float* eb2 = (const float*)d_in[5];
    const float* nw  = (const float*)d_in[6];
    const float* nb  = (const float*)d_in[7];
    const float* gw  = (const float*)d_in[8];
    const float* gb  = (const float*)d_in[9];
    const float* gms = (const float*)d_in[10];
    float* out = (float*)d_out;

    cudaFuncSetAttribute(k_all, cudaFuncAttributeMaxDynamicSharedMemorySize, FUS_SMEM);
    k_all<<<NBLK, 128, FUS_SMEM>>>(x, adj, ew1, eb1, ew2, eb2, nw, nb, gw, gb, gms, out);
}